// round 9
// baseline (speedup 1.0000x reference)
#include <cuda_runtime.h>
#include <cstdint>

#define B_  4
#define S_  4096
#define DM  768
#define DK  64
#define NS  8          // KV splits per q-tile
#define NJ  64         // number of 64-row q-tiles per batch

// Scratch (device globals: no allocation allowed)
__device__ float  g_Q [B_ * S_ * DK];   // [b*S+s][d]  (pre-scaled by 1/8)
__device__ float  g_Kt[B_ * DK * S_];   // [b][d][s]   (K transposed)
__device__ float  g_V [B_ * S_ * DK];   // [b*S+s][d]
__device__ float  g_Opart[B_ * NS * NJ * 64 * DK];  // unnormalized partial O
__device__ float2 g_ml   [B_ * NS * NJ * 64];       // per-row (m, l) per split

// ---------------- packed f32x2 helpers (FFMA2 path, sm_100+) ----------------
__device__ __forceinline__ void fma2(uint64_t& acc, uint64_t a, uint64_t b) {
    asm("fma.rn.f32x2 %0, %1, %2, %0;" : "+l"(acc) : "l"(a), "l"(b));
}
__device__ __forceinline__ void mul2(uint64_t& acc, uint64_t a) {
    asm("mul.rn.f32x2 %0, %0, %1;" : "+l"(acc) : "l"(a));
}
__device__ __forceinline__ uint64_t f2u(float x, float y) {
    uint64_t v; asm("mov.b64 %0, {%1,%2};" : "=l"(v) : "f"(x), "f"(y)); return v;
}
__device__ __forceinline__ float2 u2f(uint64_t v) {
    float2 f; asm("mov.b64 {%0,%1}, %2;" : "=f"(f.x), "=f"(f.y) : "l"(v)); return f;
}

// =====================================================================
// Kernel 1: fused QKV projection. grid = 256, block = 256. (unchanged)
// One block computes a 64-row stripe of Q, K, V together (x read ONCE).
// K is written TRANSPOSED to g_Kt[b][d][s]; Q is pre-scaled by 0.125.
// =====================================================================
#define XS_STRIDE 20    // floats per x row (16 + 4 pad)
#define WS_STRIDE 208   // floats per kk row (3*68 + 4 pad)

__global__ __launch_bounds__(256) void proj_kernel(
    const float* __restrict__ x,
    const float* __restrict__ WQ,
    const float* __restrict__ WK,
    const float* __restrict__ WV)
{
    __shared__ float xs[64 * XS_STRIDE];   // [r][kk]
    __shared__ float ws[16 * WS_STRIDE];   // [kk][w*68 + n]

    const int tid = threadIdx.x;
    const int ty = tid >> 4;        // 0..15 -> rows ty*4..+3
    const int tx = tid & 15;        // 0..15 -> cols tx*4..+3
    const int row0 = blockIdx.x * 64;

    const float* __restrict__ Wp0 = WQ;
    const float* __restrict__ Wp1 = WK;
    const float* __restrict__ Wp2 = WV;

    const int xr_r = tid >> 2, xr_c = tid & 3;        // x: 64 rows x 4 float4
    const int w_kk = tid >> 4, w_n4 = tid & 15;       // W: 16 kk x 16 float4 (per W)

    float4 xr = *reinterpret_cast<const float4*>(&x[(row0 + xr_r) * DM + xr_c * 4]);
    float4 wr0 = *reinterpret_cast<const float4*>(&Wp0[w_kk * DK + w_n4 * 4]);
    float4 wr1 = *reinterpret_cast<const float4*>(&Wp1[w_kk * DK + w_n4 * 4]);
    float4 wr2 = *reinterpret_cast<const float4*>(&Wp2[w_kk * DK + w_n4 * 4]);

    uint64_t acc[3][4][2];
#pragma unroll
    for (int w = 0; w < 3; w++)
#pragma unroll
        for (int i = 0; i < 4; i++) { acc[w][i][0] = 0ull; acc[w][i][1] = 0ull; }

    for (int k0 = 0; k0 < DM; k0 += 16) {
        __syncthreads();
        *reinterpret_cast<float4*>(&xs[xr_r * XS_STRIDE + xr_c * 4]) = xr;
        *reinterpret_cast<float4*>(&ws[w_kk * WS_STRIDE + 0 * 68 + w_n4 * 4]) = wr0;
        *reinterpret_cast<float4*>(&ws[w_kk * WS_STRIDE + 1 * 68 + w_n4 * 4]) = wr1;
        *reinterpret_cast<float4*>(&ws[w_kk * WS_STRIDE + 2 * 68 + w_n4 * 4]) = wr2;
        __syncthreads();

        if (k0 + 16 < DM) {
            xr  = *reinterpret_cast<const float4*>(&x[(row0 + xr_r) * DM + k0 + 16 + xr_c * 4]);
            wr0 = *reinterpret_cast<const float4*>(&Wp0[(k0 + 16 + w_kk) * DK + w_n4 * 4]);
            wr1 = *reinterpret_cast<const float4*>(&Wp1[(k0 + 16 + w_kk) * DK + w_n4 * 4]);
            wr2 = *reinterpret_cast<const float4*>(&Wp2[(k0 + 16 + w_kk) * DK + w_n4 * 4]);
        }

#pragma unroll
        for (int kg = 0; kg < 4; kg++) {
            float4 av[4];
#pragma unroll
            for (int i = 0; i < 4; i++)
                av[i] = *reinterpret_cast<const float4*>(&xs[(ty * 4 + i) * XS_STRIDE + kg * 4]);
#pragma unroll
            for (int sub = 0; sub < 4; sub++) {
                const int kk = kg * 4 + sub;
                ulonglong2 b0 = *reinterpret_cast<const ulonglong2*>(&ws[kk * WS_STRIDE + 0 * 68 + tx * 4]);
                ulonglong2 b1 = *reinterpret_cast<const ulonglong2*>(&ws[kk * WS_STRIDE + 1 * 68 + tx * 4]);
                ulonglong2 b2 = *reinterpret_cast<const ulonglong2*>(&ws[kk * WS_STRIDE + 2 * 68 + tx * 4]);
#pragma unroll
                for (int i = 0; i < 4; i++) {
                    float q = (&av[i].x)[sub];
                    uint64_t a = f2u(q, q);
                    fma2(acc[0][i][0], a, b0.x); fma2(acc[0][i][1], a, b0.y);
                    fma2(acc[1][i][0], a, b1.x); fma2(acc[1][i][1], a, b1.y);
                    fma2(acc[2][i][0], a, b2.x); fma2(acc[2][i][1], a, b2.y);
                }
            }
        }
    }

    // Epilogue
    const int b  = row0 >> 12;
    const int s0 = row0 & (S_ - 1);
    float kv[4][4];
#pragma unroll
    for (int i = 0; i < 4; i++) {
        const int r = row0 + ty * 4 + i;
        float2 qa = u2f(acc[0][i][0]), qb = u2f(acc[0][i][1]);
        float4 qo = make_float4(qa.x * 0.125f, qa.y * 0.125f, qb.x * 0.125f, qb.y * 0.125f);
        *reinterpret_cast<float4*>(&g_Q[r * DK + tx * 4]) = qo;
        float2 va = u2f(acc[2][i][0]), vb = u2f(acc[2][i][1]);
        *reinterpret_cast<float4*>(&g_V[r * DK + tx * 4]) = make_float4(va.x, va.y, vb.x, vb.y);
        float2 ka = u2f(acc[1][i][0]), kb = u2f(acc[1][i][1]);
        kv[i][0] = ka.x; kv[i][1] = ka.y; kv[i][2] = kb.x; kv[i][3] = kb.y;
    }
#pragma unroll
    for (int c = 0; c < 4; c++) {
        float4 kc = make_float4(kv[0][c], kv[1][c], kv[2][c], kv[3][c]);
        *reinterpret_cast<float4*>(&g_Kt[(b * DK + tx * 4 + c) * S_ + s0 + ty * 4]) = kc;
    }
}

// =====================================================================
// Kernel 2: split-KV causal flash attention, BQ=64, 4x8 thread tile.
// grid = (NJ, 4, NS), block = 128. Thread (ty 0..15, tx 0..7) owns
// 4 rows x 8 cols -> each q-splat feeds 4 FMA2 (f2u count halved) and
// softmax row reductions are 3-deep (8 lanes).
// ps overlays ks. 52.2KB smem + <=128 regs -> 4 blocks/SM.
// =====================================================================
#define TS 68                       // padded tile stride (floats)
#define OFF_QS 0                    // qs [64][TS]            (17408 B)
#define OFF_KS (64 * TS)            // ks [64 d][TS keys]     (17408 B)
#define OFF_PS OFF_KS               // ps [64 r][TS s] OVERLAYS ks
#define OFF_VS (OFF_KS + 64 * TS)   // vs [64 s][TS d]        (17408 B)
#define SMEM_TOTAL ((OFF_VS + 64 * TS) * 4)   // 52224 bytes

__global__ __launch_bounds__(128, 4) void attn_kernel()
{
    extern __shared__ float sm[];
    float* qs = sm + OFF_QS;
    float* ks = sm + OFF_KS;
    float* vs = sm + OFF_VS;
    float* ps = sm + OFF_PS;   // overlays ks

    const int tid = threadIdx.x;
    const int ty = tid >> 3;   // 0..15 -> rows ty*4..+3
    const int tx = tid & 7;    // 0..7  -> cols tx*8..+7
    const int b = blockIdx.y;
    const int j = blockIdx.x;            // 64-row q-tile index
    const int split = blockIdx.z;
    const int q0 = j * 64;
    const int nkv = j + 1;               // KV tiles of 64 keys
    const int per = (nkv + NS - 1) / NS;
    const int t0 = split * per;
    const int t1 = min(nkv, t0 + per);
    if (t0 >= t1) return;   // empty split (uniform across block)

    const float* __restrict__ Qb  = g_Q  + b * (S_ * DK);
    const float* __restrict__ Ktb = g_Kt + b * (DK * S_);
    const float* __restrict__ Vb  = g_V  + b * (S_ * DK);

    // Load Q tile (64 x 64) row-major, already scaled
#pragma unroll
    for (int i = 0; i < 8; i++) {
        int lin = tid + i * 128;
        int d4 = lin & 15, r = lin >> 4;
        *reinterpret_cast<float4*>(&qs[r * TS + d4 * 4]) =
            *reinterpret_cast<const float4*>(&Qb[(q0 + r) * DK + d4 * 4]);
    }

    uint64_t o2[4][4];
    float m[4], l[4];
#pragma unroll
    for (int i = 0; i < 4; i++) {
#pragma unroll
        for (int c = 0; c < 4; c++) o2[i][c] = 0ull;
        m[i] = -1e30f; l[i] = 0.0f;
    }

    for (int t = t0; t < t1; t++) {
        const int k0 = t * 64;
        __syncthreads();   // all GEMM2 readers done -> ks/ps/vs free

        // K tile: ks[d][key] straight from g_Kt; V tile: vs[s][d]
#pragma unroll
        for (int i = 0; i < 8; i++) {
            int lin = tid + i * 128;
            int c4 = lin & 15, rr = lin >> 4;
            *reinterpret_cast<float4*>(&ks[rr * TS + c4 * 4]) =
                *reinterpret_cast<const float4*>(&Ktb[rr * S_ + k0 + c4 * 4]);
            *reinterpret_cast<float4*>(&vs[rr * TS + c4 * 4]) =
                *reinterpret_cast<const float4*>(&Vb[(k0 + rr) * DK + c4 * 4]);
        }
        __syncthreads();

        // GEMM1: S = Q @ K^T (contract over d). 4 rows x 8 cols per thread.
        uint64_t s2[4][4];
#pragma unroll
        for (int i = 0; i < 4; i++)
#pragma unroll
            for (int c = 0; c < 4; c++) s2[i][c] = 0ull;
#pragma unroll
        for (int d0 = 0; d0 < 64; d0 += 4) {
            float4 qv[4];
#pragma unroll
            for (int i = 0; i < 4; i++)
                qv[i] = *reinterpret_cast<const float4*>(&qs[(ty * 4 + i) * TS + d0]);
#pragma unroll
            for (int sub = 0; sub < 4; sub++) {
                ulonglong2 k01 = *reinterpret_cast<const ulonglong2*>(&ks[(d0 + sub) * TS + tx * 8]);
                ulonglong2 k23 = *reinterpret_cast<const ulonglong2*>(&ks[(d0 + sub) * TS + tx * 8 + 4]);
#pragma unroll
                for (int i = 0; i < 4; i++) {
                    float q = (&qv[i].x)[sub];
                    uint64_t a = f2u(q, q);
                    fma2(s2[i][0], a, k01.x); fma2(s2[i][1], a, k01.y);
                    fma2(s2[i][2], a, k23.x); fma2(s2[i][3], a, k23.y);
                }
            }
        }

        __syncthreads();   // ks fully consumed by ALL warps -> ps may overlay it

        // Online softmax update (masking only at the global diagonal tile)
        const bool maskt = (t == nkv - 1);
#pragma unroll
        for (int i = 0; i < 4; i++) {
            float pp[8];
            float2 f0 = u2f(s2[i][0]), f1 = u2f(s2[i][1]);
            float2 f2_ = u2f(s2[i][2]), f3 = u2f(s2[i][3]);
            pp[0] = f0.x; pp[1] = f0.y; pp[2] = f1.x; pp[3] = f1.y;
            pp[4] = f2_.x; pp[5] = f2_.y; pp[6] = f3.x; pp[7] = f3.y;
            if (maskt) {
                int qrow = q0 + ty * 4 + i;
#pragma unroll
                for (int jn = 0; jn < 8; jn++)
                    if (k0 + tx * 8 + jn > qrow) pp[jn] = -1e30f;
            }
            float mi = pp[0];
#pragma unroll
            for (int jn = 1; jn < 8; jn++) mi = fmaxf(mi, pp[jn]);
#pragma unroll
            for (int off = 4; off > 0; off >>= 1)
                mi = fmaxf(mi, __shfl_xor_sync(0xffffffffu, mi, off));
            float mnew = fmaxf(m[i], mi);
            float alpha = __expf(m[i] - mnew);
            float rs = 0.0f;
#pragma unroll
            for (int jn = 0; jn < 8; jn++) {
                float p = __expf(pp[jn] - mnew);
                pp[jn] = p;
                rs += p;
            }
#pragma unroll
            for (int off = 4; off > 0; off >>= 1)
                rs += __shfl_xor_sync(0xffffffffu, rs, off);
            l[i] = l[i] * alpha + rs;
            m[i] = mnew;
            uint64_t a2 = f2u(alpha, alpha);
            mul2(o2[i][0], a2); mul2(o2[i][1], a2);
            mul2(o2[i][2], a2); mul2(o2[i][3], a2);
            // P store (row-major, conflict-free); same-warp produce/consume
            *reinterpret_cast<float4*>(&ps[(ty * 4 + i) * TS + tx * 8]) =
                make_float4(pp[0], pp[1], pp[2], pp[3]);
            *reinterpret_cast<float4*>(&ps[(ty * 4 + i) * TS + tx * 8 + 4]) =
                make_float4(pp[4], pp[5], pp[6], pp[7]);
        }
        __syncwarp();

        // GEMM2: O += P @ V (contract over s). 4 rows x 8 cols per thread.
#pragma unroll
        for (int s0 = 0; s0 < 64; s0 += 4) {
            float4 pv[4];
#pragma unroll
            for (int i = 0; i < 4; i++)
                pv[i] = *reinterpret_cast<const float4*>(&ps[(ty * 4 + i) * TS + s0]);
#pragma unroll
            for (int sub = 0; sub < 4; sub++) {
                ulonglong2 v01 = *reinterpret_cast<const ulonglong2*>(&vs[(s0 + sub) * TS + tx * 8]);
                ulonglong2 v23 = *reinterpret_cast<const ulonglong2*>(&vs[(s0 + sub) * TS + tx * 8 + 4]);
#pragma unroll
                for (int i = 0; i < 4; i++) {
                    float p = (&pv[i].x)[sub];
                    uint64_t a = f2u(p, p);
                    fma2(o2[i][0], a, v01.x); fma2(o2[i][1], a, v01.y);
                    fma2(o2[i][2], a, v23.x); fma2(o2[i][3], a, v23.y);
                }
            }
        }
    }

    // Epilogue: write UNNORMALIZED partial O + (m, l)
    const int base = ((b * NS + split) * NJ + j) * 64;
#pragma unroll
    for (int i = 0; i < 4; i++) {
        const int r = ty * 4 + i;
        ulonglong2 oA; oA.x = o2[i][0]; oA.y = o2[i][1];
        ulonglong2 oB; oB.x = o2[i][2]; oB.y = o2[i][3];
        *reinterpret_cast<ulonglong2*>(&g_Opart[(base + r) * DK + tx * 8]) = oA;
        *reinterpret_cast<ulonglong2*>(&g_Opart[(base + r) * DK + tx * 8 + 4]) = oB;
        if (tx == 0) g_ml[base + r] = make_float2(m[i], l[i]);
    }
}

// =====================================================================
// Kernel 3: combine partials. grid = (NJ, 4), block = 256.
// Thread handles one row-quarter: r = tid>>2 (0..63), 16 cols.
// =====================================================================
__global__ __launch_bounds__(256) void combine_kernel(float* __restrict__ out)
{
    const int j = blockIdx.x, b = blockIdx.y;
    const int tid = threadIdx.x;
    const int r = tid >> 2;
    const int c0 = (tid & 3) * 16;
    const int nkv = j + 1;
    const int per = (nkv + NS - 1) / NS;
    const int nsp = (nkv + per - 1) / per;   // non-empty splits

    float mv[NS], lv[NS];
    float M = -1e30f;
    for (int s = 0; s < nsp; s++) {
        float2 ml = g_ml[((b * NS + s) * NJ + j) * 64 + r];
        mv[s] = ml.x; lv[s] = ml.y;
        M = fmaxf(M, mv[s]);
    }
    float L = 0.0f, w[NS];
    for (int s = 0; s < nsp; s++) {
        w[s] = __expf(mv[s] - M);
        L += w[s] * lv[s];
    }
    const float inv = 1.0f / L;

    float4 acc[4];
#pragma unroll
    for (int q = 0; q < 4; q++) acc[q] = make_float4(0.f, 0.f, 0.f, 0.f);

    for (int s = 0; s < nsp; s++) {
        const float* Op = &g_Opart[(((b * NS + s) * NJ + j) * 64 + r) * DK + c0];
        const float ws = w[s];
#pragma unroll
        for (int q = 0; q < 4; q++) {
            float4 v = *reinterpret_cast<const float4*>(Op + q * 4);
            acc[q].x += ws * v.x; acc[q].y += ws * v.y;
            acc[q].z += ws * v.z; acc[q].w += ws * v.w;
        }
    }

    float* op = &out[((b * S_) + j * 64 + r) * DK + c0];
#pragma unroll
    for (int q = 0; q < 4; q++) {
        float4 v = make_float4(acc[q].x * inv, acc[q].y * inv,
                               acc[q].z * inv, acc[q].w * inv);
        *reinterpret_cast<float4*>(op + q * 4) = v;
    }
}

// =====================================================================
extern "C" void kernel_launch(void* const* d_in, const int* in_sizes, int n_in,
                              void* d_out, int out_size)
{
    const float* x  = (const float*)d_in[0];
    const float* WQ = (const float*)d_in[1];
    const float* WK = (const float*)d_in[2];
    const float* WV = (const float*)d_in[3];
    float* out = (float*)d_out;

    (void)in_sizes; (void)n_in; (void)out_size;

    cudaFuncSetAttribute(attn_kernel, cudaFuncAttributeMaxDynamicSharedMemorySize, SMEM_TOTAL);

    proj_kernel<<<256, 256>>>(x, WQ, WK, WV);
    attn_kernel<<<dim3(NJ, 4, NS), 128, SMEM_TOTAL>>>();
    combine_kernel<<<dim3(NJ, 4), 256>>>(out);
}

// round 11
// speedup vs baseline: 1.5284x; 1.5284x over previous
#include <cuda_runtime.h>
#include <cuda_bf16.h>
#include <cstdint>

#define B_  4
#define S_  4096
#define DM  768
#define DK  64
#define NS  8          // KV splits per q-tile
#define NJ  64         // number of 64-row q-tiles per batch
#define PN  192        // proj MMA N (WQ|WK|WV)

// Scratch (device globals: no allocation allowed)
__device__ float  g_Q [B_ * S_ * DK];   // [b*S+s][d]  (pre-scaled by 1/8)
__device__ float  g_Kt[B_ * DK * S_];   // [b][d][s]   (K transposed)
__device__ float  g_V [B_ * S_ * DK];   // [b*S+s][d]
__device__ float  g_Opart[B_ * NS * NJ * 64 * DK];  // unnormalized partial O
__device__ float2 g_ml   [B_ * NS * NJ * 64];       // per-row (m, l) per split
__device__ __nv_bfloat16 g_Wbh[PN * DM];   // W^T hi  [n][k]
__device__ __nv_bfloat16 g_Wbl[PN * DM];   // W^T lo  [n][k]

// ---------------- packed f32x2 helpers (FFMA2 path, sm_100+) ----------------
__device__ __forceinline__ void fma2(uint64_t& acc, uint64_t a, uint64_t b) {
    asm("fma.rn.f32x2 %0, %1, %2, %0;" : "+l"(acc) : "l"(a), "l"(b));
}
__device__ __forceinline__ void mul2(uint64_t& acc, uint64_t a) {
    asm("mul.rn.f32x2 %0, %0, %1;" : "+l"(acc) : "l"(a));
}
__device__ __forceinline__ uint64_t f2u(float x, float y) {
    uint64_t v; asm("mov.b64 %0, {%1,%2};" : "=l"(v) : "f"(x), "f"(y)); return v;
}
__device__ __forceinline__ float2 u2f(uint64_t v) {
    float2 f; asm("mov.b64 {%0,%1}, %2;" : "=f"(f.x), "=f"(f.y) : "l"(v)); return f;
}

// ---------------- legacy tensor-core helpers (sm_80 baseline PTX) -----------
__device__ __forceinline__ uint32_t smem_u32(const void* p) {
    uint32_t a;
    asm("{ .reg .u64 t; cvta.to.shared.u64 t, %1; cvt.u32.u64 %0, t; }"
        : "=r"(a) : "l"(p));
    return a;
}
__device__ __forceinline__ void ldm_x4(uint32_t* r, uint32_t addr) {
    asm volatile("ldmatrix.sync.aligned.m8n8.x4.shared.b16 {%0,%1,%2,%3}, [%4];"
                 : "=r"(r[0]), "=r"(r[1]), "=r"(r[2]), "=r"(r[3]) : "r"(addr));
}
__device__ __forceinline__ void mma_bf16(float* d, const uint32_t* a,
                                         uint32_t b0, uint32_t b1) {
    asm volatile("mma.sync.aligned.m16n8k16.row.col.f32.bf16.bf16.f32 "
                 "{%0,%1,%2,%3}, {%4,%5,%6,%7}, {%8,%9}, {%0,%1,%2,%3};"
                 : "+f"(d[0]), "+f"(d[1]), "+f"(d[2]), "+f"(d[3])
                 : "r"(a[0]), "r"(a[1]), "r"(a[2]), "r"(a[3]), "r"(b0), "r"(b1));
}

// =====================================================================
// Kernel 0: prep W — transpose + bf16 hi/lo split of [WQ|WK|WV].
// grid = (PN), block = 256. g_Wb*[n][k], n: 0-63 Q, 64-127 K, 128-191 V.
// =====================================================================
__global__ __launch_bounds__(256) void prep_w(
    const float* __restrict__ WQ,
    const float* __restrict__ WK,
    const float* __restrict__ WV)
{
    const int n = blockIdx.x;
    const float* W = (n < 64) ? WQ : ((n < 128) ? WK : WV);
    const int col = n & 63;
    const int tid = threadIdx.x;
#pragma unroll
    for (int e = 0; e < 3; e++) {
        const int k = tid * 3 + e;
        float v = W[k * DK + col];
        __nv_bfloat16 h = __float2bfloat16_rn(v);
        __nv_bfloat16 l = __float2bfloat16_rn(v - __bfloat162float(h));
        g_Wbh[n * DM + k] = h;
        g_Wbl[n * DM + k] = l;
    }
}

// =====================================================================
// Kernel 1: QKV projection via mma.sync bf16x3 (fp32 accum).
// grid = 128 (row tiles of 128), block = 256 (8 warps).
// Warp w computes rows w*16..+15 x all 192 cols; 24 m16n8k16 tiles.
// A/B staged in SMEM as bf16 hi/lo with 144B row stride (conflict-free
// ldmatrix). Split: Ah*Bh + Ah*Bl + Al*Bh.
// =====================================================================
#define ASM_AH 0
#define ASM_AL (128 * 144)               // 18432
#define ASM_BH (2 * 128 * 144)           // 36864
#define ASM_BL (ASM_BH + PN * 144)       // 64512
#define PSM_TOTAL (ASM_BL + PN * 144)    // 92160

__global__ __launch_bounds__(256, 1) void proj_kernel(const float* __restrict__ x)
{
    extern __shared__ char smraw[];
    const uint32_t smb = smem_u32(smraw);
    const int tid = threadIdx.x;
    const int w = tid >> 5;
    const int lane = tid & 31;
    const int row0 = blockIdx.x * 128;

    float acc[24][4];
#pragma unroll
    for (int nt = 0; nt < 24; nt++)
#pragma unroll
        for (int q = 0; q < 4; q++) acc[nt][q] = 0.0f;

    // ldmatrix lane address components
    const uint32_t aOff = (uint32_t)(w * 16 + (lane & 15)) * 144 + (uint32_t)((lane >> 4) * 16);
    const uint32_t bRow = (uint32_t)((lane & 7) | ((lane & 16) >> 1));
    const uint32_t bKo  = (uint32_t)(((lane >> 3) & 1) * 16);

    for (int kc = 0; kc < DM / 64; kc++) {
        const int k0 = kc * 64;
        __syncthreads();   // previous chunk's ldmatrix reads done

        // Convert A chunk: x[row0..+127][k0..+63] -> bf16 hi/lo (144B stride)
#pragma unroll
        for (int i = 0; i < 4; i++) {
            const int item = i * 256 + tid;      // 1024 items: 128 rows x 8 groups
            const int r = item >> 3, gp = item & 7;
            const float* src = &x[(row0 + r) * DM + k0 + gp * 8];
            float4 a = *reinterpret_cast<const float4*>(src);
            float4 b = *reinterpret_cast<const float4*>(src + 4);
            __nv_bfloat162 h0 = __floats2bfloat162_rn(a.x, a.y);
            __nv_bfloat162 h1 = __floats2bfloat162_rn(a.z, a.w);
            __nv_bfloat162 h2 = __floats2bfloat162_rn(b.x, b.y);
            __nv_bfloat162 h3 = __floats2bfloat162_rn(b.z, b.w);
            float2 f0 = __bfloat1622float2(h0), f1 = __bfloat1622float2(h1);
            float2 f2_ = __bfloat1622float2(h2), f3 = __bfloat1622float2(h3);
            __nv_bfloat162 l0 = __floats2bfloat162_rn(a.x - f0.x, a.y - f0.y);
            __nv_bfloat162 l1 = __floats2bfloat162_rn(a.z - f1.x, a.w - f1.y);
            __nv_bfloat162 l2 = __floats2bfloat162_rn(b.x - f2_.x, b.y - f2_.y);
            __nv_bfloat162 l3 = __floats2bfloat162_rn(b.z - f3.x, b.w - f3.y);
            uint4 hv, lv;
            hv.x = *reinterpret_cast<uint32_t*>(&h0); hv.y = *reinterpret_cast<uint32_t*>(&h1);
            hv.z = *reinterpret_cast<uint32_t*>(&h2); hv.w = *reinterpret_cast<uint32_t*>(&h3);
            lv.x = *reinterpret_cast<uint32_t*>(&l0); lv.y = *reinterpret_cast<uint32_t*>(&l1);
            lv.z = *reinterpret_cast<uint32_t*>(&l2); lv.w = *reinterpret_cast<uint32_t*>(&l3);
            const uint32_t off = (uint32_t)(r * 144 + gp * 16);
            *reinterpret_cast<uint4*>(smraw + ASM_AH + off) = hv;
            *reinterpret_cast<uint4*>(smraw + ASM_AL + off) = lv;
        }
        // Copy B chunk from pre-split g_Wb*: [n][k0..+63]
#pragma unroll
        for (int i = 0; i < 6; i++) {
            const int item = i * 256 + tid;      // 1536 items: 192 rows x 8 groups
            const int n = item >> 3, gp = item & 7;
            uint4 hv = *reinterpret_cast<const uint4*>(&g_Wbh[n * DM + k0 + gp * 8]);
            uint4 lv = *reinterpret_cast<const uint4*>(&g_Wbl[n * DM + k0 + gp * 8]);
            const uint32_t off = (uint32_t)(n * 144 + gp * 16);
            *reinterpret_cast<uint4*>(smraw + ASM_BH + off) = hv;
            *reinterpret_cast<uint4*>(smraw + ASM_BL + off) = lv;
        }
        __syncthreads();

#pragma unroll
        for (int ks = 0; ks < 4; ks++) {
            uint32_t ah[4], al[4];
            ldm_x4(ah, smb + ASM_AH + aOff + ks * 32);
            ldm_x4(al, smb + ASM_AL + aOff + ks * 32);
#pragma unroll
            for (int np = 0; np < 12; np++) {
                const uint32_t bo = (uint32_t)(np * 16 + bRow) * 144 + bKo + ks * 32;
                uint32_t bh[4], bl[4];
                ldm_x4(bh, smb + ASM_BH + bo);
                ldm_x4(bl, smb + ASM_BL + bo);
                mma_bf16(acc[2 * np],     ah, bh[0], bh[1]);
                mma_bf16(acc[2 * np + 1], ah, bh[2], bh[3]);
                mma_bf16(acc[2 * np],     ah, bl[0], bl[1]);
                mma_bf16(acc[2 * np + 1], ah, bl[2], bl[3]);
                mma_bf16(acc[2 * np],     al, bh[0], bh[1]);
                mma_bf16(acc[2 * np + 1], al, bh[2], bh[3]);
            }
        }
    }

    // Epilogue. Fragment layout: d0,d1 -> (row g, cols c2,c2+1); d2,d3 -> row g+8.
    const int g = lane >> 2;
    const int c2 = (lane & 3) * 2;
    const int r0g = row0 + w * 16 + g;
#pragma unroll
    for (int nt = 0; nt < 8; nt++) {
        const int col = nt * 8 + c2;
        *reinterpret_cast<float2*>(&g_Q[r0g * DK + col]) =
            make_float2(acc[nt][0] * 0.125f, acc[nt][1] * 0.125f);
        *reinterpret_cast<float2*>(&g_Q[(r0g + 8) * DK + col]) =
            make_float2(acc[nt][2] * 0.125f, acc[nt][3] * 0.125f);
        const int ntv = nt + 16;
        *reinterpret_cast<float2*>(&g_V[r0g * DK + col]) =
            make_float2(acc[ntv][0], acc[ntv][1]);
        *reinterpret_cast<float2*>(&g_V[(r0g + 8) * DK + col]) =
            make_float2(acc[ntv][2], acc[ntv][3]);
    }

    // K (n-tiles 8..15 -> d = col-64): stage [d][s] in SMEM (overlays A), then
    // coalesced store to g_Kt.
    __syncthreads();
    float* stage = reinterpret_cast<float*>(smraw);   // [64][136] f32 = 34816 B
    const int srow = w * 16 + g;
#pragma unroll
    for (int nt = 8; nt < 16; nt++) {
        const int d = (nt - 8) * 8 + c2;
        stage[d * 136 + srow]           = acc[nt][0];
        stage[(d + 1) * 136 + srow]     = acc[nt][1];
        stage[d * 136 + srow + 8]       = acc[nt][2];
        stage[(d + 1) * 136 + srow + 8] = acc[nt][3];
    }
    __syncthreads();
    const int bb = row0 >> 12;
    const int s0 = row0 & (S_ - 1);
#pragma unroll
    for (int i = 0; i < 8; i++) {
        const int item = i * 256 + tid;   // 2048 items: 64 d x 32 float4
        const int d = item >> 5, s4 = item & 31;
        float4 v = *reinterpret_cast<const float4*>(&stage[d * 136 + s4 * 4]);
        *reinterpret_cast<float4*>(&g_Kt[(bb * DK + d) * S_ + s0 + s4 * 4]) = v;
    }
}

// =====================================================================
// Kernel 2: split-KV causal flash attention, BQ=64 (round-8 winner).
// grid = (NJ, 4, NS), block = 128. Thread (ty 0..7, tx 0..15) owns
// 8 rows x 4 cols. ps overlays ks. 52.2KB smem, 4 blocks/SM.
// =====================================================================
#define TS 68
#define OFF_QS 0
#define OFF_KS (64 * TS)
#define OFF_PS OFF_KS
#define OFF_VS (OFF_KS + 64 * TS)
#define ATTN_SMEM ((OFF_VS + 64 * TS) * 4)   // 52224 bytes

__global__ __launch_bounds__(128, 4) void attn_kernel()
{
    extern __shared__ float sm[];
    float* qs = sm + OFF_QS;
    float* ks = sm + OFF_KS;
    float* vs = sm + OFF_VS;
    float* ps = sm + OFF_PS;   // overlays ks

    const int tid = threadIdx.x;
    const int ty = tid >> 4;   // 0..7  -> rows ty*8..+7
    const int tx = tid & 15;   // 0..15 -> cols tx*4..+3
    const int b = blockIdx.y;
    const int j = blockIdx.x;
    const int split = blockIdx.z;
    const int q0 = j * 64;
    const int nkv = j + 1;
    const int per = (nkv + NS - 1) / NS;
    const int t0 = split * per;
    const int t1 = min(nkv, t0 + per);
    if (t0 >= t1) return;

    const float* __restrict__ Qb  = g_Q  + b * (S_ * DK);
    const float* __restrict__ Ktb = g_Kt + b * (DK * S_);
    const float* __restrict__ Vb  = g_V  + b * (S_ * DK);

#pragma unroll
    for (int i = 0; i < 8; i++) {
        int lin = tid + i * 128;
        int d4 = lin & 15, r = lin >> 4;
        *reinterpret_cast<float4*>(&qs[r * TS + d4 * 4]) =
            *reinterpret_cast<const float4*>(&Qb[(q0 + r) * DK + d4 * 4]);
    }

    uint64_t o2[8][2];
    float m[8], l[8];
#pragma unroll
    for (int i = 0; i < 8; i++) {
        o2[i][0] = 0ull; o2[i][1] = 0ull;
        m[i] = -1e30f; l[i] = 0.0f;
    }

    for (int t = t0; t < t1; t++) {
        const int k0 = t * 64;
        __syncthreads();

#pragma unroll
        for (int i = 0; i < 8; i++) {
            int lin = tid + i * 128;
            int c4 = lin & 15, rr = lin >> 4;
            *reinterpret_cast<float4*>(&ks[rr * TS + c4 * 4]) =
                *reinterpret_cast<const float4*>(&Ktb[rr * S_ + k0 + c4 * 4]);
            *reinterpret_cast<float4*>(&vs[rr * TS + c4 * 4]) =
                *reinterpret_cast<const float4*>(&Vb[(k0 + rr) * DK + c4 * 4]);
        }
        __syncthreads();

        uint64_t s2[8][2];
#pragma unroll
        for (int i = 0; i < 8; i++) { s2[i][0] = 0ull; s2[i][1] = 0ull; }
#pragma unroll
        for (int d0 = 0; d0 < 64; d0 += 4) {
#pragma unroll
            for (int h = 0; h < 2; h++) {
                float4 qv[4];
#pragma unroll
                for (int i = 0; i < 4; i++)
                    qv[i] = *reinterpret_cast<const float4*>(&qs[(ty * 8 + h * 4 + i) * TS + d0]);
#pragma unroll
                for (int sub = 0; sub < 4; sub++) {
                    ulonglong2 kk = *reinterpret_cast<const ulonglong2*>(&ks[(d0 + sub) * TS + tx * 4]);
#pragma unroll
                    for (int i = 0; i < 4; i++) {
                        float q = (&qv[i].x)[sub];
                        uint64_t a = f2u(q, q);
                        fma2(s2[h * 4 + i][0], a, kk.x); fma2(s2[h * 4 + i][1], a, kk.y);
                    }
                }
            }
        }

        __syncthreads();

        const bool maskt = (t == nkv - 1);
#pragma unroll
        for (int i = 0; i < 8; i++) {
            float pp[4];
            float2 a = u2f(s2[i][0]);
            float2 c = u2f(s2[i][1]);
            pp[0] = a.x; pp[1] = a.y; pp[2] = c.x; pp[3] = c.y;
            if (maskt) {
                int qrow = q0 + ty * 8 + i;
#pragma unroll
                for (int jn = 0; jn < 4; jn++)
                    if (k0 + tx * 4 + jn > qrow) pp[jn] = -1e30f;
            }
            float mi = fmaxf(fmaxf(pp[0], pp[1]), fmaxf(pp[2], pp[3]));
#pragma unroll
            for (int off = 8; off > 0; off >>= 1)
                mi = fmaxf(mi, __shfl_xor_sync(0xffffffffu, mi, off));
            float mnew = fmaxf(m[i], mi);
            float alpha = __expf(m[i] - mnew);
            float rs = 0.0f;
#pragma unroll
            for (int jn = 0; jn < 4; jn++) {
                float p = __expf(pp[jn] - mnew);
                pp[jn] = p;
                rs += p;
            }
#pragma unroll
            for (int off = 8; off > 0; off >>= 1)
                rs += __shfl_xor_sync(0xffffffffu, rs, off);
            l[i] = l[i] * alpha + rs;
            m[i] = mnew;
            uint64_t a2 = f2u(alpha, alpha);
            mul2(o2[i][0], a2); mul2(o2[i][1], a2);
            *reinterpret_cast<float4*>(&ps[(ty * 8 + i) * TS + tx * 4]) =
                make_float4(pp[0], pp[1], pp[2], pp[3]);
        }
        __syncwarp();

#pragma unroll
        for (int s0 = 0; s0 < 64; s0 += 4) {
#pragma unroll
            for (int h = 0; h < 2; h++) {
                float4 pv[4];
#pragma unroll
                for (int i = 0; i < 4; i++)
                    pv[i] = *reinterpret_cast<const float4*>(&ps[(ty * 8 + h * 4 + i) * TS + s0]);
#pragma unroll
                for (int sub = 0; sub < 4; sub++) {
                    ulonglong2 vv = *reinterpret_cast<const ulonglong2*>(&vs[(s0 + sub) * TS + tx * 4]);
#pragma unroll
                    for (int i = 0; i < 4; i++) {
                        float p = (&pv[i].x)[sub];
                        uint64_t a = f2u(p, p);
                        fma2(o2[h * 4 + i][0], a, vv.x); fma2(o2[h * 4 + i][1], a, vv.y);
                    }
                }
            }
        }
    }

    const int base = ((b * NS + split) * NJ + j) * 64;
#pragma unroll
    for (int i = 0; i < 8; i++) {
        const int r = ty * 8 + i;
        ulonglong2 o; o.x = o2[i][0]; o.y = o2[i][1];
        *reinterpret_cast<ulonglong2*>(&g_Opart[(base + r) * DK + tx * 4]) = o;
        if (tx == 0) g_ml[base + r] = make_float2(m[i], l[i]);
    }
}

// =====================================================================
// Kernel 3: combine partials. grid = (NJ, 4), block = 256.
// =====================================================================
__global__ __launch_bounds__(256) void combine_kernel(float* __restrict__ out)
{
    const int j = blockIdx.x, b = blockIdx.y;
    const int tid = threadIdx.x;
    const int r = tid >> 2;
    const int c0 = (tid & 3) * 16;
    const int nkv = j + 1;
    const int per = (nkv + NS - 1) / NS;
    const int nsp = (nkv + per - 1) / per;

    float mv[NS], lv[NS];
    float M = -1e30f;
    for (int s = 0; s < nsp; s++) {
        float2 ml = g_ml[((b * NS + s) * NJ + j) * 64 + r];
        mv[s] = ml.x; lv[s] = ml.y;
        M = fmaxf(M, mv[s]);
    }
    float L = 0.0f, w[NS];
    for (int s = 0; s < nsp; s++) {
        w[s] = __expf(mv[s] - M);
        L += w[s] * lv[s];
    }
    const float inv = 1.0f / L;

    float4 acc[4];
#pragma unroll
    for (int q = 0; q < 4; q++) acc[q] = make_float4(0.f, 0.f, 0.f, 0.f);

    for (int s = 0; s < nsp; s++) {
        const float* Op = &g_Opart[(((b * NS + s) * NJ + j) * 64 + r) * DK + c0];
        const float ws = w[s];
#pragma unroll
        for (int q = 0; q < 4; q++) {
            float4 v = *reinterpret_cast<const float4*>(Op + q * 4);
            acc[q].x += ws * v.x; acc[q].y += ws * v.y;
            acc[q].z += ws * v.z; acc[q].w += ws * v.w;
        }
    }

    float* op = &out[((b * S_) + j * 64 + r) * DK + c0];
#pragma unroll
    for (int q = 0; q < 4; q++) {
        float4 v = make_float4(acc[q].x * inv, acc[q].y * inv,
                               acc[q].z * inv, acc[q].w * inv);
        *reinterpret_cast<float4*>(op + q * 4) = v;
    }
}

// =====================================================================
extern "C" void kernel_launch(void* const* d_in, const int* in_sizes, int n_in,
                              void* d_out, int out_size)
{
    const float* x  = (const float*)d_in[0];
    const float* WQ = (const float*)d_in[1];
    const float* WK = (const float*)d_in[2];
    const float* WV = (const float*)d_in[3];
    float* out = (float*)d_out;

    (void)in_sizes; (void)n_in; (void)out_size;

    cudaFuncSetAttribute(proj_kernel, cudaFuncAttributeMaxDynamicSharedMemorySize, PSM_TOTAL);
    cudaFuncSetAttribute(attn_kernel, cudaFuncAttributeMaxDynamicSharedMemorySize, ATTN_SMEM);

    prep_w<<<PN, 256>>>(WQ, WK, WV);
    proj_kernel<<<128, 256, PSM_TOTAL>>>(x);
    attn_kernel<<<dim3(NJ, 4, NS), 128, ATTN_SMEM>>>();
    combine_kernel<<<dim3(NJ, 4), 256>>>(out);
}

// round 13
// speedup vs baseline: 2.7639x; 1.8084x over previous
#include <cuda_runtime.h>
#include <cuda_bf16.h>
#include <cstdint>

#define B_  4
#define S_  4096
#define DM  768
#define DK  64
#define NS  8          // KV splits per q-tile
#define NJ  64         // number of 64-row q-tiles per batch
#define PN  192        // proj MMA N (WQ|WK|WV)

// Scratch (device globals: no allocation allowed)
__device__ float  g_Opart[B_ * NS * NJ * 64 * DK];  // unnormalized partial O
__device__ float2 g_ml   [B_ * NS * NJ * 64];       // per-row (m, l) per split
__device__ __nv_bfloat16 g_Wbh[PN * DM];            // W^T hi  [n][k]
__device__ __nv_bfloat16 g_Wbl[PN * DM];            // W^T lo  [n][k]
__device__ __nv_bfloat16 g_Qbh[B_ * S_ * DK];       // Q hi [s][d] (x0.125)
__device__ __nv_bfloat16 g_Qbl[B_ * S_ * DK];       // Q lo
__device__ __nv_bfloat16 g_Kbh[B_ * S_ * DK];       // K hi [s][d]
__device__ __nv_bfloat16 g_Kbl[B_ * S_ * DK];       // K lo
__device__ __nv_bfloat16 g_Vth[B_ * DK * S_];       // V^T hi [d][s]
__device__ __nv_bfloat16 g_Vtl[B_ * DK * S_];       // V^T lo

// ---------------- legacy tensor-core helpers (sm_80 baseline PTX) -----------
__device__ __forceinline__ uint32_t smem_u32(const void* p) {
    uint32_t a;
    asm("{ .reg .u64 t; cvta.to.shared.u64 t, %1; cvt.u32.u64 %0, t; }"
        : "=r"(a) : "l"(p));
    return a;
}
__device__ __forceinline__ void ldm_x4(uint32_t* r, uint32_t addr) {
    asm volatile("ldmatrix.sync.aligned.m8n8.x4.shared.b16 {%0,%1,%2,%3}, [%4];"
                 : "=r"(r[0]), "=r"(r[1]), "=r"(r[2]), "=r"(r[3]) : "r"(addr));
}
__device__ __forceinline__ void mma_bf16(float* d, const uint32_t* a,
                                         uint32_t b0, uint32_t b1) {
    asm volatile("mma.sync.aligned.m16n8k16.row.col.f32.bf16.bf16.f32 "
                 "{%0,%1,%2,%3}, {%4,%5,%6,%7}, {%8,%9}, {%0,%1,%2,%3};"
                 : "+f"(d[0]), "+f"(d[1]), "+f"(d[2]), "+f"(d[3])
                 : "r"(a[0]), "r"(a[1]), "r"(a[2]), "r"(a[3]), "r"(b0), "r"(b1));
}
__device__ __forceinline__ uint32_t bf2u(__nv_bfloat162 v) {
    return *reinterpret_cast<uint32_t*>(&v);
}
__device__ __forceinline__ void split_hl(float x, float y, uint32_t& h, uint32_t& l) {
    __nv_bfloat162 hb = __floats2bfloat162_rn(x, y);
    float2 hf = __bfloat1622float2(hb);
    __nv_bfloat162 lb = __floats2bfloat162_rn(x - hf.x, y - hf.y);
    h = bf2u(hb); l = bf2u(lb);
}

// =====================================================================
// Kernel 0: prep W — transpose + bf16 hi/lo split of [WQ|WK|WV].
// =====================================================================
__global__ __launch_bounds__(256) void prep_w(
    const float* __restrict__ WQ,
    const float* __restrict__ WK,
    const float* __restrict__ WV)
{
    const int n = blockIdx.x;
    const float* W = (n < 64) ? WQ : ((n < 128) ? WK : WV);
    const int col = n & 63;
    const int tid = threadIdx.x;
#pragma unroll
    for (int e = 0; e < 3; e++) {
        const int k = tid * 3 + e;
        float v = W[k * DK + col];
        __nv_bfloat16 h = __float2bfloat16_rn(v);
        __nv_bfloat16 l = __float2bfloat16_rn(v - __bfloat162float(h));
        g_Wbh[n * DM + k] = h;
        g_Wbl[n * DM + k] = l;
    }
}

// =====================================================================
// Kernel 1: QKV projection via mma.sync bf16x3 (fp32 accum).
// grid = 128, block = 256 (8 warps). Outputs bf16 hi/lo Q,K ([s][d])
// and V^T ([d][s]).
// =====================================================================
#define ASM_AH 0
#define ASM_AL (128 * 144)               // 18432
#define ASM_BH (2 * 128 * 144)           // 36864
#define ASM_BL (ASM_BH + PN * 144)       // 64512
#define PSM_TOTAL (ASM_BL + PN * 144)    // 92160

__global__ __launch_bounds__(256, 1) void proj_kernel(const float* __restrict__ x)
{
    extern __shared__ char smraw[];
    const uint32_t smb = smem_u32(smraw);
    const int tid = threadIdx.x;
    const int w = tid >> 5;
    const int lane = tid & 31;
    const int row0 = blockIdx.x * 128;

    float acc[24][4];
#pragma unroll
    for (int nt = 0; nt < 24; nt++)
#pragma unroll
        for (int q = 0; q < 4; q++) acc[nt][q] = 0.0f;

    const uint32_t aOff = (uint32_t)(w * 16 + (lane & 15)) * 144 + (uint32_t)((lane >> 4) * 16);
    const uint32_t bRow = (uint32_t)((lane & 7) | ((lane & 16) >> 1));
    const uint32_t bKo  = (uint32_t)(((lane >> 3) & 1) * 16);

    for (int kc = 0; kc < DM / 64; kc++) {
        const int k0 = kc * 64;
        __syncthreads();

#pragma unroll
        for (int i = 0; i < 4; i++) {
            const int item = i * 256 + tid;
            const int r = item >> 3, gp = item & 7;
            const float* src = &x[(row0 + r) * DM + k0 + gp * 8];
            float4 a = *reinterpret_cast<const float4*>(src);
            float4 b = *reinterpret_cast<const float4*>(src + 4);
            uint4 hv, lv;
            split_hl(a.x, a.y, hv.x, lv.x);
            split_hl(a.z, a.w, hv.y, lv.y);
            split_hl(b.x, b.y, hv.z, lv.z);
            split_hl(b.z, b.w, hv.w, lv.w);
            const uint32_t off = (uint32_t)(r * 144 + gp * 16);
            *reinterpret_cast<uint4*>(smraw + ASM_AH + off) = hv;
            *reinterpret_cast<uint4*>(smraw + ASM_AL + off) = lv;
        }
#pragma unroll
        for (int i = 0; i < 6; i++) {
            const int item = i * 256 + tid;
            const int n = item >> 3, gp = item & 7;
            uint4 hv = *reinterpret_cast<const uint4*>(&g_Wbh[n * DM + k0 + gp * 8]);
            uint4 lv = *reinterpret_cast<const uint4*>(&g_Wbl[n * DM + k0 + gp * 8]);
            const uint32_t off = (uint32_t)(n * 144 + gp * 16);
            *reinterpret_cast<uint4*>(smraw + ASM_BH + off) = hv;
            *reinterpret_cast<uint4*>(smraw + ASM_BL + off) = lv;
        }
        __syncthreads();

#pragma unroll
        for (int ks = 0; ks < 4; ks++) {
            uint32_t ah[4], al[4];
            ldm_x4(ah, smb + ASM_AH + aOff + ks * 32);
            ldm_x4(al, smb + ASM_AL + aOff + ks * 32);
#pragma unroll
            for (int np = 0; np < 12; np++) {
                const uint32_t bo = (uint32_t)(np * 16 + bRow) * 144 + bKo + ks * 32;
                uint32_t bh[4], bl[4];
                ldm_x4(bh, smb + ASM_BH + bo);
                ldm_x4(bl, smb + ASM_BL + bo);
                mma_bf16(acc[2 * np],     ah, bh[0], bh[1]);
                mma_bf16(acc[2 * np + 1], ah, bh[2], bh[3]);
                mma_bf16(acc[2 * np],     ah, bl[0], bl[1]);
                mma_bf16(acc[2 * np + 1], ah, bl[2], bl[3]);
                mma_bf16(acc[2 * np],     al, bh[0], bh[1]);
                mma_bf16(acc[2 * np + 1], al, bh[2], bh[3]);
            }
        }
    }

    // Epilogue. C-frag: (row g, cols c2,c2+1) = d0,d1; row g+8 = d2,d3.
    const int g = lane >> 2;
    const int c2 = (lane & 3) * 2;
    const int r0g = row0 + w * 16 + g;
#pragma unroll
    for (int nt = 0; nt < 8; nt++) {
        const int col = nt * 8 + c2;
        uint32_t h, l;
        // Q (x0.125)
        split_hl(acc[nt][0] * 0.125f, acc[nt][1] * 0.125f, h, l);
        *reinterpret_cast<uint32_t*>(&g_Qbh[r0g * DK + col]) = h;
        *reinterpret_cast<uint32_t*>(&g_Qbl[r0g * DK + col]) = l;
        split_hl(acc[nt][2] * 0.125f, acc[nt][3] * 0.125f, h, l);
        *reinterpret_cast<uint32_t*>(&g_Qbh[(r0g + 8) * DK + col]) = h;
        *reinterpret_cast<uint32_t*>(&g_Qbl[(r0g + 8) * DK + col]) = l;
        // K
        split_hl(acc[nt + 8][0], acc[nt + 8][1], h, l);
        *reinterpret_cast<uint32_t*>(&g_Kbh[r0g * DK + col]) = h;
        *reinterpret_cast<uint32_t*>(&g_Kbl[r0g * DK + col]) = l;
        split_hl(acc[nt + 8][2], acc[nt + 8][3], h, l);
        *reinterpret_cast<uint32_t*>(&g_Kbh[(r0g + 8) * DK + col]) = h;
        *reinterpret_cast<uint32_t*>(&g_Kbl[(r0g + 8) * DK + col]) = l;
    }

    // V: stage fp32 [d][s] in SMEM (overlays A/B), then bf16 hi/lo to g_Vt*
    __syncthreads();
    float* stage = reinterpret_cast<float*>(smraw);   // [64][136] = 34816 B
    const int srow = w * 16 + g;
#pragma unroll
    for (int nt = 16; nt < 24; nt++) {
        const int d = (nt - 16) * 8 + c2;
        stage[d * 136 + srow]           = acc[nt][0];
        stage[(d + 1) * 136 + srow]     = acc[nt][1];
        stage[d * 136 + srow + 8]       = acc[nt][2];
        stage[(d + 1) * 136 + srow + 8] = acc[nt][3];
    }
    __syncthreads();
    const int bb = row0 >> 12;
    const int s0 = row0 & (S_ - 1);
    // FIX (R12 bug): 2048 items = 64 d x 32 float4 -> FULL 128 s columns
#pragma unroll
    for (int i = 0; i < 8; i++) {
        const int item = i * 256 + tid;
        const int d = item >> 5, s4 = item & 31;
        float4 v = *reinterpret_cast<const float4*>(&stage[d * 136 + s4 * 4]);
        uint2 hv, lv;
        split_hl(v.x, v.y, hv.x, lv.x);
        split_hl(v.z, v.w, hv.y, lv.y);
        const int idx = (bb * DK + d) * S_ + s0 + s4 * 4;
        *reinterpret_cast<uint2*>(&g_Vth[idx]) = hv;
        *reinterpret_cast<uint2*>(&g_Vtl[idx]) = lv;
    }
}

// =====================================================================
// Kernel 2: split-KV causal flash attention via mma.sync bf16x3.
// grid = (NJ, 4, NS), block = 128 (4 warps). Warp w owns q-rows w*16..+15.
// GEMM1: S = Q@K^T (QhKh + QhKl + QlKh). P exp'd + hi/lo split in regs,
// repacked as A-frags (C-frag layout == A-frag layout). GEMM2: O += P@V^T
// (PhVh + PhVl + PlVh). 55.3KB smem -> 4 blocks/SM.
// =====================================================================
#define ATS 144
#define AQH 0
#define AQL (64 * ATS)
#define AKH (2 * 64 * ATS)
#define AKL (3 * 64 * ATS)
#define AVH (4 * 64 * ATS)
#define AVL (5 * 64 * ATS)
#define ATTN_SMEM (6 * 64 * ATS)    // 55296

__global__ __launch_bounds__(128, 4) void attn_kernel()
{
    extern __shared__ char smraw[];
    const uint32_t smb = smem_u32(smraw);
    const int tid = threadIdx.x;
    const int w = tid >> 5;
    const int lane = tid & 31;
    const int g = lane >> 2;
    const int qd = lane & 3;
    const int b = blockIdx.y;
    const int j = blockIdx.x;
    const int split = blockIdx.z;
    const int q0 = j * 64;
    const int nkv = j + 1;
    const int per = (nkv + NS - 1) / NS;
    const int t0 = split * per;
    const int t1 = min(nkv, t0 + per);
    if (t0 >= t1) return;

    // Load Q tile (64 x 64) bf16 hi/lo into SMEM
#pragma unroll
    for (int i = 0; i < 4; i++) {
        const int item = i * 128 + tid;   // 512 items: 64 rows x 8 groups
        const int r = item >> 3, gp = item & 7;
        const int src = (b * S_ + q0 + r) * DK + gp * 8;
        const uint32_t off = (uint32_t)(r * ATS + gp * 16);
        *reinterpret_cast<uint4*>(smraw + AQH + off) =
            *reinterpret_cast<const uint4*>(&g_Qbh[src]);
        *reinterpret_cast<uint4*>(smraw + AQL + off) =
            *reinterpret_cast<const uint4*>(&g_Qbl[src]);
    }

    const uint32_t aOff = (uint32_t)(w * 16 + (lane & 15)) * ATS + (uint32_t)((lane >> 4) * 16);
    const uint32_t bRow = (uint32_t)((lane & 7) | ((lane & 16) >> 1));
    const uint32_t bKo  = (uint32_t)(((lane >> 3) & 1) * 16);

    float o[8][4];
#pragma unroll
    for (int nt = 0; nt < 8; nt++)
#pragma unroll
        for (int c = 0; c < 4; c++) o[nt][c] = 0.0f;
    float m0 = -1e30f, m1 = -1e30f, l0 = 0.0f, l1 = 0.0f;

    for (int t = t0; t < t1; t++) {
        const int k0 = t * 64;
        __syncthreads();   // previous tile's ldmatrix reads done (and Q stores on t0)

        // Load K [key][d] and V^T [d][s] bf16 hi/lo tiles
#pragma unroll
        for (int i = 0; i < 4; i++) {
            const int item = i * 128 + tid;
            const int r = item >> 3, gp = item & 7;
            const uint32_t off = (uint32_t)(r * ATS + gp * 16);
            const int ksrc = (b * S_ + k0 + r) * DK + gp * 8;
            const int vsrc = (b * DK + r) * S_ + k0 + gp * 8;
            *reinterpret_cast<uint4*>(smraw + AKH + off) =
                *reinterpret_cast<const uint4*>(&g_Kbh[ksrc]);
            *reinterpret_cast<uint4*>(smraw + AKL + off) =
                *reinterpret_cast<const uint4*>(&g_Kbl[ksrc]);
            *reinterpret_cast<uint4*>(smraw + AVH + off) =
                *reinterpret_cast<const uint4*>(&g_Vth[vsrc]);
            *reinterpret_cast<uint4*>(smraw + AVL + off) =
                *reinterpret_cast<const uint4*>(&g_Vtl[vsrc]);
        }
        __syncthreads();

        // GEMM1: S = Q @ K^T (bf16x3)
        float s[8][4];
#pragma unroll
        for (int nt = 0; nt < 8; nt++)
#pragma unroll
            for (int c = 0; c < 4; c++) s[nt][c] = 0.0f;
#pragma unroll
        for (int kc = 0; kc < 4; kc++) {
            uint32_t ah[4], al[4];
            ldm_x4(ah, smb + AQH + aOff + kc * 32);
            ldm_x4(al, smb + AQL + aOff + kc * 32);
#pragma unroll
            for (int np = 0; np < 4; np++) {
                const uint32_t bo = (uint32_t)(np * 16 + bRow) * ATS + bKo + kc * 32;
                uint32_t kh[4], kl[4];
                ldm_x4(kh, smb + AKH + bo);
                ldm_x4(kl, smb + AKL + bo);
                mma_bf16(s[2 * np],     ah, kh[0], kh[1]);
                mma_bf16(s[2 * np + 1], ah, kh[2], kh[3]);
                mma_bf16(s[2 * np],     ah, kl[0], kl[1]);
                mma_bf16(s[2 * np + 1], ah, kl[2], kl[3]);
                mma_bf16(s[2 * np],     al, kh[0], kh[1]);
                mma_bf16(s[2 * np + 1], al, kh[2], kh[3]);
            }
        }

        // Online softmax + P hi/lo pack (registers only)
        const bool maskt = (t == nkv - 1);
        uint32_t ph0[8], pl0[8], ph1[8], pl1[8];
        {   // row 0 (g): c0, c1
            const int qrow = q0 + w * 16 + g;
            if (maskt) {
#pragma unroll
                for (int nt = 0; nt < 8; nt++) {
                    const int key = k0 + nt * 8 + 2 * qd;
                    if (key > qrow)     s[nt][0] = -1e30f;
                    if (key + 1 > qrow) s[nt][1] = -1e30f;
                }
            }
            float mi = -1e30f;
#pragma unroll
            for (int nt = 0; nt < 8; nt++)
                mi = fmaxf(mi, fmaxf(s[nt][0], s[nt][1]));
            mi = fmaxf(mi, __shfl_xor_sync(0xffffffffu, mi, 1));
            mi = fmaxf(mi, __shfl_xor_sync(0xffffffffu, mi, 2));
            const float mnew = fmaxf(m0, mi);
            const float alpha = __expf(m0 - mnew);
            float rs = 0.0f;
#pragma unroll
            for (int nt = 0; nt < 8; nt++) {
                float p0 = __expf(s[nt][0] - mnew);
                float p1 = __expf(s[nt][1] - mnew);
                rs += p0 + p1;
                split_hl(p0, p1, ph0[nt], pl0[nt]);
                o[nt][0] *= alpha; o[nt][1] *= alpha;
            }
            rs += __shfl_xor_sync(0xffffffffu, rs, 1);
            rs += __shfl_xor_sync(0xffffffffu, rs, 2);
            l0 = l0 * alpha + rs;
            m0 = mnew;
        }
        {   // row 1 (g+8): c2, c3
            const int qrow = q0 + w * 16 + g + 8;
            if (maskt) {
#pragma unroll
                for (int nt = 0; nt < 8; nt++) {
                    const int key = k0 + nt * 8 + 2 * qd;
                    if (key > qrow)     s[nt][2] = -1e30f;
                    if (key + 1 > qrow) s[nt][3] = -1e30f;
                }
            }
            float mi = -1e30f;
#pragma unroll
            for (int nt = 0; nt < 8; nt++)
                mi = fmaxf(mi, fmaxf(s[nt][2], s[nt][3]));
            mi = fmaxf(mi, __shfl_xor_sync(0xffffffffu, mi, 1));
            mi = fmaxf(mi, __shfl_xor_sync(0xffffffffu, mi, 2));
            const float mnew = fmaxf(m1, mi);
            const float alpha = __expf(m1 - mnew);
            float rs = 0.0f;
#pragma unroll
            for (int nt = 0; nt < 8; nt++) {
                float p0 = __expf(s[nt][2] - mnew);
                float p1 = __expf(s[nt][3] - mnew);
                rs += p0 + p1;
                split_hl(p0, p1, ph1[nt], pl1[nt]);
                o[nt][2] *= alpha; o[nt][3] *= alpha;
            }
            rs += __shfl_xor_sync(0xffffffffu, rs, 1);
            rs += __shfl_xor_sync(0xffffffffu, rs, 2);
            l1 = l1 * alpha + rs;
            m1 = mnew;
        }

        // GEMM2: O += P @ V^T (bf16x3); A-frags direct from P registers
#pragma unroll
        for (int kc = 0; kc < 4; kc++) {
            uint32_t aH[4] = { ph0[2 * kc], ph1[2 * kc], ph0[2 * kc + 1], ph1[2 * kc + 1] };
            uint32_t aL[4] = { pl0[2 * kc], pl1[2 * kc], pl0[2 * kc + 1], pl1[2 * kc + 1] };
#pragma unroll
            for (int np = 0; np < 4; np++) {
                const uint32_t bo = (uint32_t)(np * 16 + bRow) * ATS + bKo + kc * 32;
                uint32_t vh[4], vl[4];
                ldm_x4(vh, smb + AVH + bo);
                ldm_x4(vl, smb + AVL + bo);
                mma_bf16(o[2 * np],     aH, vh[0], vh[1]);
                mma_bf16(o[2 * np + 1], aH, vh[2], vh[3]);
                mma_bf16(o[2 * np],     aH, vl[0], vl[1]);
                mma_bf16(o[2 * np + 1], aH, vl[2], vl[3]);
                mma_bf16(o[2 * np],     aL, vh[0], vh[1]);
                mma_bf16(o[2 * np + 1], aL, vh[2], vh[3]);
            }
        }
    }

    // Epilogue: write UNNORMALIZED partial O + (m, l)
    const int base = ((b * NS + split) * NJ + j) * 64;
    const int row0 = w * 16 + g;
    const int row1 = row0 + 8;
#pragma unroll
    for (int nt = 0; nt < 8; nt++) {
        const int col = nt * 8 + 2 * qd;
        *reinterpret_cast<float2*>(&g_Opart[(base + row0) * DK + col]) =
            make_float2(o[nt][0], o[nt][1]);
        *reinterpret_cast<float2*>(&g_Opart[(base + row1) * DK + col]) =
            make_float2(o[nt][2], o[nt][3]);
    }
    if (qd == 0) {
        g_ml[base + row0] = make_float2(m0, l0);
        g_ml[base + row1] = make_float2(m1, l1);
    }
}

// =====================================================================
// Kernel 3: combine partials. grid = (NJ, 4), block = 256.
// =====================================================================
__global__ __launch_bounds__(256) void combine_kernel(float* __restrict__ out)
{
    const int j = blockIdx.x, b = blockIdx.y;
    const int tid = threadIdx.x;
    const int r = tid >> 2;
    const int c0 = (tid & 3) * 16;
    const int nkv = j + 1;
    const int per = (nkv + NS - 1) / NS;
    const int nsp = (nkv + per - 1) / per;

    float mv[NS], lv[NS];
    float M = -1e30f;
    for (int s = 0; s < nsp; s++) {
        float2 ml = g_ml[((b * NS + s) * NJ + j) * 64 + r];
        mv[s] = ml.x; lv[s] = ml.y;
        M = fmaxf(M, mv[s]);
    }
    float L = 0.0f, ww[NS];
    for (int s = 0; s < nsp; s++) {
        ww[s] = __expf(mv[s] - M);
        L += ww[s] * lv[s];
    }
    const float inv = 1.0f / L;

    float4 acc[4];
#pragma unroll
    for (int q = 0; q < 4; q++) acc[q] = make_float4(0.f, 0.f, 0.f, 0.f);

    for (int s = 0; s < nsp; s++) {
        const float* Op = &g_Opart[(((b * NS + s) * NJ + j) * 64 + r) * DK + c0];
        const float ws = ww[s];
#pragma unroll
        for (int q = 0; q < 4; q++) {
            float4 v = *reinterpret_cast<const float4*>(Op + q * 4);
            acc[q].x += ws * v.x; acc[q].y += ws * v.y;
            acc[q].z += ws * v.z; acc[q].w += ws * v.w;
        }
    }

    float* op = &out[((b * S_) + j * 64 + r) * DK + c0];
#pragma unroll
    for (int q = 0; q < 4; q++) {
        float4 v = make_float4(acc[q].x * inv, acc[q].y * inv,
                               acc[q].z * inv, acc[q].w * inv);
        *reinterpret_cast<float4*>(op + q * 4) = v;
    }
}

// =====================================================================
extern "C" void kernel_launch(void* const* d_in, const int* in_sizes, int n_in,
                              void* d_out, int out_size)
{
    const float* x  = (const float*)d_in[0];
    const float* WQ = (const float*)d_in[1];
    const float* WK = (const float*)d_in[2];
    const float* WV = (const float*)d_in[3];
    float* out = (float*)d_out;

    (void)in_sizes; (void)n_in; (void)out_size;

    cudaFuncSetAttribute(proj_kernel, cudaFuncAttributeMaxDynamicSharedMemorySize, PSM_TOTAL);
    cudaFuncSetAttribute(attn_kernel, cudaFuncAttributeMaxDynamicSharedMemorySize, ATTN_SMEM);

    prep_w<<<PN, 256>>>(WQ, WK, WV);
    proj_kernel<<<128, 256, PSM_TOTAL>>>(x);
    attn_kernel<<<dim3(NJ, 4, NS), 128, ATTN_SMEM>>>();
    combine_kernel<<<dim3(NJ, 4), 256>>>(out);
}